// round 1
// baseline (speedup 1.0000x reference)
#include <cuda_runtime.h>
#include <math.h>

// ---- problem constants ----
#define OC     128
#define IC     64
#define SPAN   576          // IC * 3 * 3
#define TSIZE  8            // LSH table size
#define MLSH   5            // ALSH m
#define HH     56
#define WW     56
#define BATCH  16
#define IMG    (HH*WW)      // 3136
#define NPIX   (BATCH*IMG)  // 50176

// ---- device scratch (no allocations allowed) ----
__device__ int   g_counts[TSIZE];
__device__ float g_factor[OC];

// bucket(h) = abs(fmod(int(floor((h+b)/2.5)), 8))  -- matches reference exactly
__device__ __forceinline__ int bucket_of(float h, float b) {
    float q = floorf((h + b) / 2.5f);
    int i = (int)q;          // truncation of integer-valued float: exact
    int r = i % TSIZE;       // C %: sign of dividend, same as fmod on int
    return r < 0 ? -r : r;
}

__global__ void init_counts_kernel() {
    if (threadIdx.x < TSIZE) g_counts[threadIdx.x] = 0;
}

// ------------------------------------------------------------------
// Vote pass: hash each im2col patch column, histogram into 8 buckets.
// One thread per output pixel. x layout [B, IC, H, W].
// ------------------------------------------------------------------
__global__ __launch_bounds__(256) void vote_kernel(
    const float* __restrict__ x,
    const float* __restrict__ a,
    const float* __restrict__ bptr)
{
    __shared__ float sa[SPAN + MLSH];
    __shared__ int hist[TSIZE];
    for (int i = threadIdx.x; i < SPAN + MLSH; i += blockDim.x) sa[i] = a[i];
    if (threadIdx.x < TSIZE) hist[threadIdx.x] = 0;
    __syncthreads();

    int n = blockIdx.x * blockDim.x + threadIdx.x;  // grid sized exactly NPIX
    {
        int b   = n / IMG;
        int pix = n % IMG;
        int y   = pix / WW;
        int xc  = pix % WW;

        float v = 0.0f;
        const float* xb = x + (size_t)b * IC * IMG;
        for (int c = 0; c < IC; c++) {
            const float* xp = xb + c * IMG;
            const float* ap = sa + c * 9;
            #pragma unroll
            for (int dy = 0; dy < 3; dy++) {
                int yy = y + dy - 1;
                if ((unsigned)yy < HH) {
                    const float* row = xp + yy * WW;
                    #pragma unroll
                    for (int dx = 0; dx < 3; dx++) {
                        int xx = xc + dx - 1;
                        if ((unsigned)xx < WW) v += ap[dy*3 + dx] * row[xx];
                    }
                }
            }
        }
        // Q-augmentation: + 0.5 * sum(a[SPAN:])
        float q = 0.0f;
        #pragma unroll
        for (int i = 0; i < MLSH; i++) q += sa[SPAN + i];
        v += 0.5f * q;

        int bu = bucket_of(v, bptr[0]);
        atomicAdd(&hist[bu], 1);
    }
    __syncthreads();
    if (threadIdx.x < TSIZE) atomicAdd(&g_counts[threadIdx.x], hist[threadIdx.x]);
}

// ------------------------------------------------------------------
// Kernel-row hashes + winning bucket + per-channel factor.
// One block, 128 threads (one per output channel).
// ------------------------------------------------------------------
__global__ __launch_bounds__(128) void factor_kernel(
    const float* __restrict__ kernels,
    const float* __restrict__ a,
    const float* __restrict__ bptr)
{
    __shared__ float sa[SPAN + MLSH];
    __shared__ int sh_bucket;
    __shared__ int sh_cnt;
    for (int i = threadIdx.x; i < SPAN + MLSH; i += blockDim.x) sa[i] = a[i];
    if (threadIdx.x == 0) {
        // first-max argmax over counts (matches jnp.argmax tie-breaking)
        int best = 0, bi = 0;
        #pragma unroll
        for (int t = 0; t < TSIZE; t++) {
            int c = g_counts[t];
            if (c > best) { best = c; bi = t; }
        }
        sh_bucket = bi;
        sh_cnt = 0;
    }
    __syncthreads();

    int oc = threadIdx.x;
    const float* w = kernels + (size_t)oc * SPAN;
    float dot = 0.0f, nrm = 0.0f;
    for (int k = 0; k < SPAN; k++) {
        float wv = w[k];
        dot += wv * sa[k];
        nrm += wv * wv;
    }
    // P-augmentation: sum_i norms2^(2^i) * a[SPAN+i], via repeated squaring
    float s = nrm, paug = 0.0f;
    #pragma unroll
    for (int i = 0; i < MLSH; i++) {
        paug += s * sa[SPAN + i];
        s = s * s;
    }
    float hk = dot + paug;
    int kidx = bucket_of(hk, bptr[0]);

    int in_bucket = (kidx == sh_bucket) ? 1 : 0;
    atomicAdd(&sh_cnt, in_bucket);
    __syncthreads();

    int cnt = sh_cnt;
    float f;
    if (cnt > 0) f = in_bucket ? ((float)OC / (float)cnt) : 0.0f;
    else         f = 1.0f;   // empty bucket -> dense conv, no rescale
    g_factor[oc] = f;
}

// ------------------------------------------------------------------
// Implicit GEMM: out[OC, NPIX] = (kernels * factor) @ patches
// BM=128 (all OC), BN=128 pixels, BK=8, 256 threads, 8x8 per thread.
// ------------------------------------------------------------------
#define BM 128
#define BN 128
#define BK 8

__global__ __launch_bounds__(256) void conv_gemm_kernel(
    const float* __restrict__ W,     // kernels [OC, SPAN]
    const float* __restrict__ x,     // [B, IC, H, W]
    float* __restrict__ out)         // [B, OC, H, W]
{
    __shared__ float Ws[BK][BM];
    __shared__ float Ps[BK][BN];

    const int tid = threadIdx.x;
    const int n0  = blockIdx.x * BN;
    const int ty  = tid >> 4;        // 0..15
    const int tx  = tid & 15;        // 0..15

    // W staging: thread -> (row wm, 4 consecutive k at wk)
    const int wm = tid >> 1;
    const int wk = (tid & 1) * 4;
    const float fac = g_factor[wm];

    // P staging: thread -> (k-row pk, 4 consecutive n at pn)
    const int pk = tid >> 5;
    const int pn = (tid & 31) * 4;

    float acc[8][8];
    #pragma unroll
    for (int i = 0; i < 8; i++)
        #pragma unroll
        for (int j = 0; j < 8; j++) acc[i][j] = 0.0f;

    for (int k0 = 0; k0 < SPAN; k0 += BK) {
        // --- gather W fragment (global, coalesced float4 per row pair) ---
        float4 wv = *(const float4*)(W + (size_t)wm * SPAN + k0 + wk);

        // --- gather P fragment: 4 patch elements for k = k0+pk ---
        float pv[4];
        {
            int k  = k0 + pk;
            int c  = k / 9;
            int r  = k % 9;
            int dy = r / 3 - 1;
            int dx = r % 3 - 1;
            const float* xc_base = x + (size_t)c * IMG;
            #pragma unroll
            for (int j = 0; j < 4; j++) {
                int n   = n0 + pn + j;
                int b   = n / IMG;
                int pix = n % IMG;
                int y   = pix / WW + dy;
                int xx  = pix % WW + dx;
                float val = 0.0f;
                if ((unsigned)y < HH && (unsigned)xx < WW)
                    val = xc_base[(size_t)b * IC * IMG + y * WW + xx];
                pv[j] = val;
            }
        }

        __syncthreads();   // previous iteration's smem reads done
        Ws[wk + 0][wm] = wv.x * fac;
        Ws[wk + 1][wm] = wv.y * fac;
        Ws[wk + 2][wm] = wv.z * fac;
        Ws[wk + 3][wm] = wv.w * fac;
        *(float4*)&Ps[pk][pn] = make_float4(pv[0], pv[1], pv[2], pv[3]);
        __syncthreads();

        // --- 128x128x8 rank-1 updates, 8x8 per thread ---
        #pragma unroll
        for (int kk = 0; kk < BK; kk++) {
            float wr[8], pr[8];
            #pragma unroll
            for (int i = 0; i < 8; i++) wr[i] = Ws[kk][ty * 8 + i];
            #pragma unroll
            for (int j = 0; j < 8; j++) pr[j] = Ps[kk][tx * 8 + j];
            #pragma unroll
            for (int i = 0; i < 8; i++)
                #pragma unroll
                for (int j = 0; j < 8; j++) acc[i][j] += wr[i] * pr[j];
        }
    }

    // --- epilogue: out[b, m, pix] ---
    #pragma unroll
    for (int i = 0; i < 8; i++) {
        int m = ty * 8 + i;
        #pragma unroll
        for (int j = 0; j < 8; j++) {
            int n   = n0 + tx * 8 + j;
            int b   = n / IMG;
            int pix = n % IMG;
            out[((size_t)b * OC + m) * IMG + pix] = acc[i][j];
        }
    }
}

// ------------------------------------------------------------------
extern "C" void kernel_launch(void* const* d_in, const int* in_sizes, int n_in,
                              void* d_out, int out_size)
{
    const float* x       = (const float*)d_in[0];  // [16,64,56,56]
    const float* kernels = (const float*)d_in[1];  // [128,576]
    const float* a       = (const float*)d_in[2];  // [581]
    const float* b       = (const float*)d_in[3];  // scalar
    // d_in[4] = mode (unused, mode==0)
    float* out = (float*)d_out;

    init_counts_kernel<<<1, 32>>>();
    vote_kernel<<<NPIX / 256, 256>>>(x, a, b);          // 196 blocks, exact
    factor_kernel<<<1, 128>>>(kernels, a, b);
    conv_gemm_kernel<<<NPIX / BN, 256>>>(kernels, x, out);  // 392 blocks, exact
}

// round 2
// speedup vs baseline: 1.0017x; 1.0017x over previous
#include <cuda_runtime.h>
#include <math.h>

// ---- problem constants ----
#define OC     128
#define IC     64
#define SPAN   576          // IC * 3 * 3
#define TSIZE  8            // LSH table size
#define MLSH   5            // ALSH m
#define HH     56
#define WW     56
#define BATCH  16
#define IMG    (HH*WW)      // 3136
#define NPIX   (BATCH*IMG)  // 50176

// ---- device scratch (no allocations allowed) ----
__device__ int   g_counts[TSIZE];
__device__ float g_factor[OC];

// bucket(h) = abs(fmod(int(floor((h+b)/2.5)), 8))  -- matches reference exactly
__device__ __forceinline__ int bucket_of(float h, float b) {
    float q = floorf((h + b) / 2.5f);
    int i = (int)q;          // truncation of integer-valued float: exact
    int r = i % TSIZE;       // C %: sign of dividend, same as fmod on int
    return r < 0 ? -r : r;
}

__global__ void init_counts_kernel() {
    if (threadIdx.x < TSIZE) g_counts[threadIdx.x] = 0;
}

// ------------------------------------------------------------------
// Vote pass: hash each im2col patch column, histogram into 8 buckets.
// One thread per output pixel. x layout [B, IC, H, W].
// ------------------------------------------------------------------
__global__ __launch_bounds__(256) void vote_kernel(
    const float* __restrict__ x,
    const float* __restrict__ a,
    const float* __restrict__ bptr)
{
    __shared__ float sa[SPAN + MLSH];
    __shared__ int hist[TSIZE];
    for (int i = threadIdx.x; i < SPAN + MLSH; i += blockDim.x) sa[i] = a[i];
    if (threadIdx.x < TSIZE) hist[threadIdx.x] = 0;
    __syncthreads();

    int n = blockIdx.x * blockDim.x + threadIdx.x;  // grid sized exactly NPIX
    {
        int b   = n / IMG;
        int pix = n % IMG;
        int y   = pix / WW;
        int xc  = pix % WW;

        float v = 0.0f;
        const float* xb = x + (size_t)b * IC * IMG;
        for (int c = 0; c < IC; c++) {
            const float* xp = xb + c * IMG;
            const float* ap = sa + c * 9;
            #pragma unroll
            for (int dy = 0; dy < 3; dy++) {
                int yy = y + dy - 1;
                if ((unsigned)yy < HH) {
                    const float* row = xp + yy * WW;
                    #pragma unroll
                    for (int dx = 0; dx < 3; dx++) {
                        int xx = xc + dx - 1;
                        if ((unsigned)xx < WW) v += ap[dy*3 + dx] * row[xx];
                    }
                }
            }
        }
        // Q-augmentation: + 0.5 * sum(a[SPAN:])
        float q = 0.0f;
        #pragma unroll
        for (int i = 0; i < MLSH; i++) q += sa[SPAN + i];
        v += 0.5f * q;

        int bu = bucket_of(v, bptr[0]);
        atomicAdd(&hist[bu], 1);
    }
    __syncthreads();
    if (threadIdx.x < TSIZE) atomicAdd(&g_counts[threadIdx.x], hist[threadIdx.x]);
}

// ------------------------------------------------------------------
// Kernel-row hashes + winning bucket + per-channel factor.
// One block, 128 threads (one per output channel).
// ------------------------------------------------------------------
__global__ __launch_bounds__(128) void factor_kernel(
    const float* __restrict__ kernels,
    const float* __restrict__ a,
    const float* __restrict__ bptr)
{
    __shared__ float sa[SPAN + MLSH];
    __shared__ int sh_bucket;
    __shared__ int sh_cnt;
    for (int i = threadIdx.x; i < SPAN + MLSH; i += blockDim.x) sa[i] = a[i];
    if (threadIdx.x == 0) {
        // first-max argmax over counts (matches jnp.argmax tie-breaking)
        int best = 0, bi = 0;
        #pragma unroll
        for (int t = 0; t < TSIZE; t++) {
            int c = g_counts[t];
            if (c > best) { best = c; bi = t; }
        }
        sh_bucket = bi;
        sh_cnt = 0;
    }
    __syncthreads();

    int oc = threadIdx.x;
    const float* w = kernels + (size_t)oc * SPAN;
    float dot = 0.0f, nrm = 0.0f;
    for (int k = 0; k < SPAN; k++) {
        float wv = w[k];
        dot += wv * sa[k];
        nrm += wv * wv;
    }
    // P-augmentation: sum_i norms2^(2^i) * a[SPAN+i], via repeated squaring
    float s = nrm, paug = 0.0f;
    #pragma unroll
    for (int i = 0; i < MLSH; i++) {
        paug += s * sa[SPAN + i];
        s = s * s;
    }
    float hk = dot + paug;
    int kidx = bucket_of(hk, bptr[0]);

    int in_bucket = (kidx == sh_bucket) ? 1 : 0;
    atomicAdd(&sh_cnt, in_bucket);
    __syncthreads();

    int cnt = sh_cnt;
    float f;
    if (cnt > 0) f = in_bucket ? ((float)OC / (float)cnt) : 0.0f;
    else         f = 1.0f;   // empty bucket -> dense conv, no rescale
    g_factor[oc] = f;
}

// ------------------------------------------------------------------
// Implicit GEMM: out[OC, NPIX] = (kernels * factor) @ patches
// BM=128 (all OC), BN=128 pixels, BK=8, 256 threads, 8x8 per thread.
// ------------------------------------------------------------------
#define BM 128
#define BN 128
#define BK 8

__global__ __launch_bounds__(256) void conv_gemm_kernel(
    const float* __restrict__ W,     // kernels [OC, SPAN]
    const float* __restrict__ x,     // [B, IC, H, W]
    float* __restrict__ out)         // [B, OC, H, W]
{
    __shared__ float Ws[BK][BM];
    __shared__ float Ps[BK][BN];

    const int tid = threadIdx.x;
    const int n0  = blockIdx.x * BN;
    const int ty  = tid >> 4;        // 0..15
    const int tx  = tid & 15;        // 0..15

    // W staging: thread -> (row wm, 4 consecutive k at wk)
    const int wm = tid >> 1;
    const int wk = (tid & 1) * 4;
    const float fac = g_factor[wm];

    // P staging: thread -> (k-row pk, 4 consecutive n at pn)
    const int pk = tid >> 5;
    const int pn = (tid & 31) * 4;

    float acc[8][8];
    #pragma unroll
    for (int i = 0; i < 8; i++)
        #pragma unroll
        for (int j = 0; j < 8; j++) acc[i][j] = 0.0f;

    for (int k0 = 0; k0 < SPAN; k0 += BK) {
        // --- gather W fragment (global, coalesced float4 per row pair) ---
        float4 wv = *(const float4*)(W + (size_t)wm * SPAN + k0 + wk);

        // --- gather P fragment: 4 patch elements for k = k0+pk ---
        float pv[4];
        {
            int k  = k0 + pk;
            int c  = k / 9;
            int r  = k % 9;
            int dy = r / 3 - 1;
            int dx = r % 3 - 1;
            const float* xc_base = x + (size_t)c * IMG;
            #pragma unroll
            for (int j = 0; j < 4; j++) {
                int n   = n0 + pn + j;
                int b   = n / IMG;
                int pix = n % IMG;
                int y   = pix / WW + dy;
                int xx  = pix % WW + dx;
                float val = 0.0f;
                if ((unsigned)y < HH && (unsigned)xx < WW)
                    val = xc_base[(size_t)b * IC * IMG + y * WW + xx];
                pv[j] = val;
            }
        }

        __syncthreads();   // previous iteration's smem reads done
        Ws[wk + 0][wm] = wv.x * fac;
        Ws[wk + 1][wm] = wv.y * fac;
        Ws[wk + 2][wm] = wv.z * fac;
        Ws[wk + 3][wm] = wv.w * fac;
        *(float4*)&Ps[pk][pn] = make_float4(pv[0], pv[1], pv[2], pv[3]);
        __syncthreads();

        // --- 128x128x8 rank-1 updates, 8x8 per thread ---
        #pragma unroll
        for (int kk = 0; kk < BK; kk++) {
            float wr[8], pr[8];
            #pragma unroll
            for (int i = 0; i < 8; i++) wr[i] = Ws[kk][ty * 8 + i];
            #pragma unroll
            for (int j = 0; j < 8; j++) pr[j] = Ps[kk][tx * 8 + j];
            #pragma unroll
            for (int i = 0; i < 8; i++)
                #pragma unroll
                for (int j = 0; j < 8; j++) acc[i][j] += wr[i] * pr[j];
        }
    }

    // --- epilogue: out[b, m, pix] ---
    #pragma unroll
    for (int i = 0; i < 8; i++) {
        int m = ty * 8 + i;
        #pragma unroll
        for (int j = 0; j < 8; j++) {
            int n   = n0 + tx * 8 + j;
            int b   = n / IMG;
            int pix = n % IMG;
            out[((size_t)b * OC + m) * IMG + pix] = acc[i][j];
        }
    }
}

// ------------------------------------------------------------------
extern "C" void kernel_launch(void* const* d_in, const int* in_sizes, int n_in,
                              void* d_out, int out_size)
{
    const float* x       = (const float*)d_in[0];  // [16,64,56,56]
    const float* kernels = (const float*)d_in[1];  // [128,576]
    const float* a       = (const float*)d_in[2];  // [581]
    const float* b       = (const float*)d_in[3];  // scalar
    // d_in[4] = mode (unused, mode==0)
    float* out = (float*)d_out;

    init_counts_kernel<<<1, 32>>>();
    vote_kernel<<<NPIX / 256, 256>>>(x, a, b);          // 196 blocks, exact
    factor_kernel<<<1, 128>>>(kernels, a, b);
    conv_gemm_kernel<<<NPIX / BN, 256>>>(kernels, x, out);  // 392 blocks, exact
}

// round 3
// speedup vs baseline: 1.0050x; 1.0033x over previous
#include <cuda_runtime.h>
#include <math.h>

// ---- problem constants ----
#define OC     128
#define IC     64
#define SPAN   576          // IC * 3 * 3
#define TSIZE  8            // LSH table size
#define MLSH   5            // ALSH m
#define HH     56
#define WW     56
#define BATCH  16
#define IMG    (HH*WW)      // 3136
#define NPIX   (BATCH*IMG)  // 50176

// ---- device scratch (no allocations allowed) ----
__device__ int   g_counts[TSIZE];
__device__ float g_factor[OC];

// bucket(h) = abs(fmod(int(floor((h+b)/2.5)), 8))  -- matches reference exactly
__device__ __forceinline__ int bucket_of(float h, float b) {
    float q = floorf((h + b) / 2.5f);
    int i = (int)q;          // truncation of integer-valued float: exact
    int r = i % TSIZE;       // C %: sign of dividend, same as fmod on int
    return r < 0 ? -r : r;
}

__global__ void init_counts_kernel() {
    if (threadIdx.x < TSIZE) g_counts[threadIdx.x] = 0;
}

// ------------------------------------------------------------------
// Vote pass: hash each im2col patch column, histogram into 8 buckets.
// One thread per output pixel. x layout [B, IC, H, W].
// ------------------------------------------------------------------
__global__ __launch_bounds__(256) void vote_kernel(
    const float* __restrict__ x,
    const float* __restrict__ a,
    const float* __restrict__ bptr)
{
    __shared__ float sa[SPAN + MLSH];
    __shared__ int hist[TSIZE];
    for (int i = threadIdx.x; i < SPAN + MLSH; i += blockDim.x) sa[i] = a[i];
    if (threadIdx.x < TSIZE) hist[threadIdx.x] = 0;
    __syncthreads();

    int n = blockIdx.x * blockDim.x + threadIdx.x;  // grid sized exactly NPIX
    {
        int b   = n / IMG;
        int pix = n % IMG;
        int y   = pix / WW;
        int xc  = pix % WW;

        float v = 0.0f;
        const float* xb = x + (size_t)b * IC * IMG;
        for (int c = 0; c < IC; c++) {
            const float* xp = xb + c * IMG;
            const float* ap = sa + c * 9;
            #pragma unroll
            for (int dy = 0; dy < 3; dy++) {
                int yy = y + dy - 1;
                if ((unsigned)yy < HH) {
                    const float* row = xp + yy * WW;
                    #pragma unroll
                    for (int dx = 0; dx < 3; dx++) {
                        int xx = xc + dx - 1;
                        if ((unsigned)xx < WW) v += ap[dy*3 + dx] * row[xx];
                    }
                }
            }
        }
        // Q-augmentation: + 0.5 * sum(a[SPAN:])
        float q = 0.0f;
        #pragma unroll
        for (int i = 0; i < MLSH; i++) q += sa[SPAN + i];
        v += 0.5f * q;

        int bu = bucket_of(v, bptr[0]);
        atomicAdd(&hist[bu], 1);
    }
    __syncthreads();
    if (threadIdx.x < TSIZE) atomicAdd(&g_counts[threadIdx.x], hist[threadIdx.x]);
}

// ------------------------------------------------------------------
// Kernel-row hashes + winning bucket + per-channel factor.
// One block, 128 threads (one per output channel).
// ------------------------------------------------------------------
__global__ __launch_bounds__(128) void factor_kernel(
    const float* __restrict__ kernels,
    const float* __restrict__ a,
    const float* __restrict__ bptr)
{
    __shared__ float sa[SPAN + MLSH];
    __shared__ int sh_bucket;
    __shared__ int sh_cnt;
    for (int i = threadIdx.x; i < SPAN + MLSH; i += blockDim.x) sa[i] = a[i];
    if (threadIdx.x == 0) {
        // first-max argmax over counts (matches jnp.argmax tie-breaking)
        int best = 0, bi = 0;
        #pragma unroll
        for (int t = 0; t < TSIZE; t++) {
            int c = g_counts[t];
            if (c > best) { best = c; bi = t; }
        }
        sh_bucket = bi;
        sh_cnt = 0;
    }
    __syncthreads();

    int oc = threadIdx.x;
    const float* w = kernels + (size_t)oc * SPAN;
    float dot = 0.0f, nrm = 0.0f;
    for (int k = 0; k < SPAN; k++) {
        float wv = w[k];
        dot += wv * sa[k];
        nrm += wv * wv;
    }
    // P-augmentation: sum_i norms2^(2^i) * a[SPAN+i], via repeated squaring
    float s = nrm, paug = 0.0f;
    #pragma unroll
    for (int i = 0; i < MLSH; i++) {
        paug += s * sa[SPAN + i];
        s = s * s;
    }
    float hk = dot + paug;
    int kidx = bucket_of(hk, bptr[0]);

    int in_bucket = (kidx == sh_bucket) ? 1 : 0;
    atomicAdd(&sh_cnt, in_bucket);
    __syncthreads();

    int cnt = sh_cnt;
    float f;
    if (cnt > 0) f = in_bucket ? ((float)OC / (float)cnt) : 0.0f;
    else         f = 1.0f;   // empty bucket -> dense conv, no rescale
    g_factor[oc] = f;
}

// ------------------------------------------------------------------
// Implicit GEMM: out[OC, NPIX] = (kernels * factor) @ patches
// BM=128 (all OC), BN=128 pixels, BK=8, 256 threads, 8x8 per thread.
// ------------------------------------------------------------------
#define BM 128
#define BN 128
#define BK 8

__global__ __launch_bounds__(256) void conv_gemm_kernel(
    const float* __restrict__ W,     // kernels [OC, SPAN]
    const float* __restrict__ x,     // [B, IC, H, W]
    float* __restrict__ out)         // [B, OC, H, W]
{
    __shared__ float Ws[BK][BM];
    __shared__ float Ps[BK][BN];

    const int tid = threadIdx.x;
    const int n0  = blockIdx.x * BN;
    const int ty  = tid >> 4;        // 0..15
    const int tx  = tid & 15;        // 0..15

    // W staging: thread -> (row wm, 4 consecutive k at wk)
    const int wm = tid >> 1;
    const int wk = (tid & 1) * 4;
    const float fac = g_factor[wm];

    // P staging: thread -> (k-row pk, 4 consecutive n at pn)
    const int pk = tid >> 5;
    const int pn = (tid & 31) * 4;

    float acc[8][8];
    #pragma unroll
    for (int i = 0; i < 8; i++)
        #pragma unroll
        for (int j = 0; j < 8; j++) acc[i][j] = 0.0f;

    for (int k0 = 0; k0 < SPAN; k0 += BK) {
        // --- gather W fragment (global, coalesced float4 per row pair) ---
        float4 wv = *(const float4*)(W + (size_t)wm * SPAN + k0 + wk);

        // --- gather P fragment: 4 patch elements for k = k0+pk ---
        float pv[4];
        {
            int k  = k0 + pk;
            int c  = k / 9;
            int r  = k % 9;
            int dy = r / 3 - 1;
            int dx = r % 3 - 1;
            const float* xc_base = x + (size_t)c * IMG;
            #pragma unroll
            for (int j = 0; j < 4; j++) {
                int n   = n0 + pn + j;
                int b   = n / IMG;
                int pix = n % IMG;
                int y   = pix / WW + dy;
                int xx  = pix % WW + dx;
                float val = 0.0f;
                if ((unsigned)y < HH && (unsigned)xx < WW)
                    val = xc_base[(size_t)b * IC * IMG + y * WW + xx];
                pv[j] = val;
            }
        }

        __syncthreads();   // previous iteration's smem reads done
        Ws[wk + 0][wm] = wv.x * fac;
        Ws[wk + 1][wm] = wv.y * fac;
        Ws[wk + 2][wm] = wv.z * fac;
        Ws[wk + 3][wm] = wv.w * fac;
        *(float4*)&Ps[pk][pn] = make_float4(pv[0], pv[1], pv[2], pv[3]);
        __syncthreads();

        // --- 128x128x8 rank-1 updates, 8x8 per thread ---
        #pragma unroll
        for (int kk = 0; kk < BK; kk++) {
            float wr[8], pr[8];
            #pragma unroll
            for (int i = 0; i < 8; i++) wr[i] = Ws[kk][ty * 8 + i];
            #pragma unroll
            for (int j = 0; j < 8; j++) pr[j] = Ps[kk][tx * 8 + j];
            #pragma unroll
            for (int i = 0; i < 8; i++)
                #pragma unroll
                for (int j = 0; j < 8; j++) acc[i][j] += wr[i] * pr[j];
        }
    }

    // --- epilogue: out[b, m, pix] ---
    #pragma unroll
    for (int i = 0; i < 8; i++) {
        int m = ty * 8 + i;
        #pragma unroll
        for (int j = 0; j < 8; j++) {
            int n   = n0 + tx * 8 + j;
            int b   = n / IMG;
            int pix = n % IMG;
            out[((size_t)b * OC + m) * IMG + pix] = acc[i][j];
        }
    }
}

// ------------------------------------------------------------------
extern "C" void kernel_launch(void* const* d_in, const int* in_sizes, int n_in,
                              void* d_out, int out_size)
{
    const float* x       = (const float*)d_in[0];  // [16,64,56,56]
    const float* kernels = (const float*)d_in[1];  // [128,576]
    const float* a       = (const float*)d_in[2];  // [581]
    const float* b       = (const float*)d_in[3];  // scalar
    // d_in[4] = mode (unused, mode==0)
    float* out = (float*)d_out;

    init_counts_kernel<<<1, 32>>>();
    vote_kernel<<<NPIX / 256, 256>>>(x, a, b);          // 196 blocks, exact
    factor_kernel<<<1, 128>>>(kernels, a, b);
    conv_gemm_kernel<<<NPIX / BN, 256>>>(kernels, x, out);  // 392 blocks, exact
}

// round 5
// speedup vs baseline: 1.6834x; 1.6749x over previous
#include <cuda_runtime.h>
#include <cuda_bf16.h>
#include <math.h>
#include <stdint.h>

// ---- problem constants ----
#define OC     128
#define IC     64
#define SPAN   576
#define TSIZE  8
#define MLSH   5
#define HH     56
#define WW     56
#define BATCH  16
#define IMG    (HH*WW)      // 3136
#define NPIX   (BATCH*IMG)  // 50176

// ---- device scratch ----
__device__ int   g_counts[TSIZE];
__device__ float g_factor[OC];

// ============================================================
// helpers
// ============================================================
__device__ __forceinline__ uint32_t smem_u32(const void* p) {
    uint32_t a;
    asm("{ .reg .u64 t; cvta.to.shared.u64 t, %1; cvt.u32.u64 %0, t; }" : "=r"(a) : "l"(p));
    return a;
}
__device__ __forceinline__ uint32_t swz(uint32_t off) { return off ^ ((off >> 3) & 0x70); }

// ldmatrix x4: 4 8x8 b16 tiles, lane-provided row addresses
__device__ __forceinline__ void ldsm_x4(uint32_t* r, uint32_t addr) {
    asm volatile("ldmatrix.sync.aligned.m8n8.x4.shared.b16 {%0,%1,%2,%3}, [%4];"
        : "=r"(r[0]), "=r"(r[1]), "=r"(r[2]), "=r"(r[3]) : "r"(addr));
}
// HMMA m16n8k16 bf16 -> fp32 (sm_80+ PTX, valid on sm_103 base target)
__device__ __forceinline__ void mma_bf16(float* c, const uint32_t* a, const uint32_t* b) {
    asm volatile(
        "mma.sync.aligned.m16n8k16.row.col.f32.bf16.bf16.f32 "
        "{%0,%1,%2,%3}, {%4,%5,%6,%7}, {%8,%9}, {%0,%1,%2,%3};"
        : "+f"(c[0]), "+f"(c[1]), "+f"(c[2]), "+f"(c[3])
        : "r"(a[0]), "r"(a[1]), "r"(a[2]), "r"(a[3]), "r"(b[0]), "r"(b[1]));
}

__device__ __forceinline__ int bucket_of(float h, float b) {
    float q = floorf((h + b) / 2.5f);
    int i = (int)q;
    int r = i % TSIZE;
    return r < 0 ? -r : r;
}

__global__ void init_counts_kernel() {
    if (threadIdx.x < TSIZE) g_counts[threadIdx.x] = 0;
}

// ------------------------------------------------------------------
// Vote pass
// ------------------------------------------------------------------
__global__ __launch_bounds__(256) void vote_kernel(
    const float* __restrict__ x, const float* __restrict__ a, const float* __restrict__ bptr)
{
    __shared__ float sa[SPAN + MLSH];
    __shared__ int hist[TSIZE];
    for (int i = threadIdx.x; i < SPAN + MLSH; i += blockDim.x) sa[i] = a[i];
    if (threadIdx.x < TSIZE) hist[threadIdx.x] = 0;
    __syncthreads();

    int n = blockIdx.x * blockDim.x + threadIdx.x;
    {
        int b = n / IMG, pix = n % IMG, y = pix / WW, xc = pix % WW;
        float v = 0.0f;
        const float* xb = x + (size_t)b * IC * IMG;
        for (int c = 0; c < IC; c++) {
            const float* xp = xb + c * IMG;
            const float* ap = sa + c * 9;
            #pragma unroll
            for (int dy = 0; dy < 3; dy++) {
                int yy = y + dy - 1;
                if ((unsigned)yy < HH) {
                    const float* row = xp + yy * WW;
                    #pragma unroll
                    for (int dx = 0; dx < 3; dx++) {
                        int xx = xc + dx - 1;
                        if ((unsigned)xx < WW) v += ap[dy*3 + dx] * row[xx];
                    }
                }
            }
        }
        float q = 0.0f;
        #pragma unroll
        for (int i = 0; i < MLSH; i++) q += sa[SPAN + i];
        v += 0.5f * q;
        atomicAdd(&hist[bucket_of(v, bptr[0])], 1);
    }
    __syncthreads();
    if (threadIdx.x < TSIZE) atomicAdd(&g_counts[threadIdx.x], hist[threadIdx.x]);
}

// ------------------------------------------------------------------
// Factor pass
// ------------------------------------------------------------------
__global__ __launch_bounds__(128) void factor_kernel(
    const float* __restrict__ kernels, const float* __restrict__ a, const float* __restrict__ bptr)
{
    __shared__ float sa[SPAN + MLSH];
    __shared__ int sh_bucket, sh_cnt;
    for (int i = threadIdx.x; i < SPAN + MLSH; i += blockDim.x) sa[i] = a[i];
    if (threadIdx.x == 0) {
        int best = 0, bi = 0;
        #pragma unroll
        for (int t = 0; t < TSIZE; t++) { int c = g_counts[t]; if (c > best) { best = c; bi = t; } }
        sh_bucket = bi; sh_cnt = 0;
    }
    __syncthreads();

    int oc = threadIdx.x;
    const float* w = kernels + (size_t)oc * SPAN;
    float dot = 0.0f, nrm = 0.0f;
    for (int k = 0; k < SPAN; k++) { float wv = w[k]; dot += wv * sa[k]; nrm += wv * wv; }
    float s = nrm, paug = 0.0f;
    #pragma unroll
    for (int i = 0; i < MLSH; i++) { paug += s * sa[SPAN + i]; s = s * s; }
    int kidx = bucket_of(dot + paug, bptr[0]);
    int in_bucket = (kidx == sh_bucket) ? 1 : 0;
    atomicAdd(&sh_cnt, in_bucket);
    __syncthreads();
    int cnt = sh_cnt;
    g_factor[oc] = (cnt > 0) ? (in_bucket ? ((float)OC / (float)cnt) : 0.0f) : 1.0f;
}

// ------------------------------------------------------------------
// HMMA bf16-split implicit GEMM
//   out[128 OC, 128 pix] = (A_hi+A_lo)(B_hi+B_lo)^T per 64-wide K chunk
//   passes: Ahi*Bhi + Ahi*Blo + Alo*Bhi  (fp32 accumulate in registers)
// 8 warps, warp tile 64x32, mma.sync m16n8k16.
// ------------------------------------------------------------------
#define KC      64                // bf16 per chunk = 128B rows
#define NCHUNK  (SPAN/KC)         // 9
#define A_HI 0
#define A_LO 16384
#define B_HI 32768
#define B_LO 49152
#define DYN_SMEM (65536 + 1024)

__global__ __launch_bounds__(256, 2)
void conv_hmma_kernel(const float* __restrict__ W,
                      const float* __restrict__ x,
                      float* __restrict__ out)
{
    extern __shared__ char dsm[];
    char* sb = (char*)(((uintptr_t)dsm + 1023) & ~(uintptr_t)1023);
    const uint32_t sb_u = smem_u32(sb);

    const int tid  = threadIdx.x;
    const int wid  = tid >> 5;
    const int lane = tid & 31;
    const int n0   = blockIdx.x * 128;

    const int wm = wid >> 2;       // 0..1 : m offset 64*wm
    const int wn = wid & 3;        // 0..3 : n offset 32*wn

    // ---- staging geometry: 2 threads per row, 32 k each ----
    const int rown  = tid >> 1;            // 0..127 (OC row for A, pixel for B)
    const int kbase = (tid & 1) * 32;
    const int n     = n0 + rown;
    const int bimg  = n / IMG;
    const int pix   = n - bimg * IMG;
    const int y0    = pix / WW;
    const int x0    = pix - y0 * WW;
    const float* xb   = x + (size_t)bimg * IC * IMG;
    const float fac   = g_factor[rown];
    const float* wrow = W + (size_t)rown * SPAN;

    // ---- ldmatrix lane address components ----
    // A (x4, m16xk16): row = base + (lane&15), +16B when lane>=16
    const uint32_t a_row  = (uint32_t)(wm * 64 + (lane & 15)) * 128 + ((lane >> 4) << 4);
    // B (x4, 2 n8-tiles x k16): rows n_base + (lane&7) + (lane>>4)*8, +16B for lanes 8-15/24-31
    const uint32_t b_row  = (uint32_t)(wn * 32 + (lane & 7) + ((lane >> 4) << 3)) * 128
                          + (((lane >> 3) & 1) << 4);

    float acc[4][4][4];
    #pragma unroll
    for (int i = 0; i < 4; i++)
        #pragma unroll
        for (int j = 0; j < 4; j++)
            #pragma unroll
            for (int q = 0; q < 4; q++) acc[i][j][q] = 0.0f;

    for (int ch = 0; ch < NCHUNK; ch++) {
        const int k0 = ch * KC;

        // ============ stage A & B tiles (split hi/lo bf16) ============
        #pragma unroll
        for (int q = 0; q < 8; q++) {
            // A: weights * factor
            float4 v = *(const float4*)(wrow + k0 + kbase + q * 4);
            v.x *= fac; v.y *= fac; v.z *= fac; v.w *= fac;
            uint32_t off0 = swz((uint32_t)(rown * 128 + (kbase + q * 4) * 2));
            uint32_t off1 = swz((uint32_t)(rown * 128 + (kbase + q * 4 + 2) * 2));
            {
                __nv_bfloat16 h0 = __float2bfloat16(v.x), h1 = __float2bfloat16(v.y);
                __nv_bfloat16 h2 = __float2bfloat16(v.z), h3 = __float2bfloat16(v.w);
                __nv_bfloat16 l0 = __float2bfloat16(v.x - __bfloat162float(h0));
                __nv_bfloat16 l1 = __float2bfloat16(v.y - __bfloat162float(h1));
                __nv_bfloat16 l2 = __float2bfloat16(v.z - __bfloat162float(h2));
                __nv_bfloat16 l3 = __float2bfloat16(v.w - __bfloat162float(h3));
                *(uint32_t*)(sb + A_HI + off0) = (uint32_t)__bfloat16_as_ushort(h0) | ((uint32_t)__bfloat16_as_ushort(h1) << 16);
                *(uint32_t*)(sb + A_HI + off1) = (uint32_t)__bfloat16_as_ushort(h2) | ((uint32_t)__bfloat16_as_ushort(h3) << 16);
                *(uint32_t*)(sb + A_LO + off0) = (uint32_t)__bfloat16_as_ushort(l0) | ((uint32_t)__bfloat16_as_ushort(l1) << 16);
                *(uint32_t*)(sb + A_LO + off1) = (uint32_t)__bfloat16_as_ushort(l2) | ((uint32_t)__bfloat16_as_ushort(l3) << 16);
            }
            // B: im2col gather (4 consecutive k)
            float bvv[4];
            #pragma unroll
            for (int j = 0; j < 4; j++) {
                int kg = k0 + kbase + q * 4 + j;
                int cc = kg / 9;
                int rr = kg - cc * 9;
                int dy = rr / 3;
                int dx = rr - dy * 3;
                int yy = y0 + dy - 1;
                int xx = x0 + dx - 1;
                float val = 0.0f;
                if ((unsigned)yy < HH && (unsigned)xx < WW)
                    val = xb[cc * IMG + yy * WW + xx];
                bvv[j] = val;
            }
            {
                __nv_bfloat16 h0 = __float2bfloat16(bvv[0]), h1 = __float2bfloat16(bvv[1]);
                __nv_bfloat16 h2 = __float2bfloat16(bvv[2]), h3 = __float2bfloat16(bvv[3]);
                __nv_bfloat16 l0 = __float2bfloat16(bvv[0] - __bfloat162float(h0));
                __nv_bfloat16 l1 = __float2bfloat16(bvv[1] - __bfloat162float(h1));
                __nv_bfloat16 l2 = __float2bfloat16(bvv[2] - __bfloat162float(h2));
                __nv_bfloat16 l3 = __float2bfloat16(bvv[3] - __bfloat162float(h3));
                *(uint32_t*)(sb + B_HI + off0) = (uint32_t)__bfloat16_as_ushort(h0) | ((uint32_t)__bfloat16_as_ushort(h1) << 16);
                *(uint32_t*)(sb + B_HI + off1) = (uint32_t)__bfloat16_as_ushort(h2) | ((uint32_t)__bfloat16_as_ushort(h3) << 16);
                *(uint32_t*)(sb + B_LO + off0) = (uint32_t)__bfloat16_as_ushort(l0) | ((uint32_t)__bfloat16_as_ushort(l1) << 16);
                *(uint32_t*)(sb + B_LO + off1) = (uint32_t)__bfloat16_as_ushort(l2) | ((uint32_t)__bfloat16_as_ushort(l3) << 16);
            }
        }
        __syncthreads();

        // ============ 4 k-steps of 16, 3 passes each ============
        #pragma unroll
        for (int ks = 0; ks < 4; ks++) {
            const uint32_t kb = (uint32_t)ks * 32;   // 16 bf16 = 32 bytes
            uint32_t af[4][4], bhf[4][2], blf[4][2];

            // A_hi fragments (4 m16 tiles)
            #pragma unroll
            for (int mt = 0; mt < 4; mt++)
                ldsm_x4(af[mt], sb_u + A_HI + swz(a_row + (uint32_t)mt * 16 * 128 + kb));
            // B_hi fragments (4 n8 tiles via 2 x4 loads)
            #pragma unroll
            for (int p = 0; p < 2; p++) {
                uint32_t t[4];
                ldsm_x4(t, sb_u + B_HI + swz(b_row + (uint32_t)p * 16 * 128 + kb));
                bhf[p*2+0][0] = t[0]; bhf[p*2+0][1] = t[1];
                bhf[p*2+1][0] = t[2]; bhf[p*2+1][1] = t[3];
            }
            // B_lo fragments
            #pragma unroll
            for (int p = 0; p < 2; p++) {
                uint32_t t[4];
                ldsm_x4(t, sb_u + B_LO + swz(b_row + (uint32_t)p * 16 * 128 + kb));
                blf[p*2+0][0] = t[0]; blf[p*2+0][1] = t[1];
                blf[p*2+1][0] = t[2]; blf[p*2+1][1] = t[3];
            }

            // pass 1: Ahi * Bhi   pass 2: Ahi * Blo
            #pragma unroll
            for (int mt = 0; mt < 4; mt++)
                #pragma unroll
                for (int nt = 0; nt < 4; nt++) {
                    mma_bf16(acc[mt][nt], af[mt], bhf[nt]);
                    mma_bf16(acc[mt][nt], af[mt], blf[nt]);
                }
            // pass 3: Alo * Bhi (A_lo overwrites af)
            #pragma unroll
            for (int mt = 0; mt < 4; mt++)
                ldsm_x4(af[mt], sb_u + A_LO + swz(a_row + (uint32_t)mt * 16 * 128 + kb));
            #pragma unroll
            for (int mt = 0; mt < 4; mt++)
                #pragma unroll
                for (int nt = 0; nt < 4; nt++)
                    mma_bf16(acc[mt][nt], af[mt], bhf[nt]);
        }
        __syncthreads();
    }

    // ============ epilogue: acc -> out[b, m, pix] ============
    #pragma unroll
    for (int mt = 0; mt < 4; mt++) {
        const int m = wm * 64 + mt * 16 + (lane >> 2);
        #pragma unroll
        for (int nt = 0; nt < 4; nt++) {
            const int np = n0 + wn * 32 + nt * 8 + (lane & 3) * 2;  // even, pair never crosses image
            const int bb = np / IMG;
            const int pp = np - bb * IMG;
            float* o0 = out + ((size_t)bb * OC + m) * IMG + pp;
            *(float2*)o0             = make_float2(acc[mt][nt][0], acc[mt][nt][1]);
            *(float2*)(o0 + 8 * IMG) = make_float2(acc[mt][nt][2], acc[mt][nt][3]);
        }
    }
}

// ------------------------------------------------------------------
extern "C" void kernel_launch(void* const* d_in, const int* in_sizes, int n_in,
                              void* d_out, int out_size)
{
    const float* x       = (const float*)d_in[0];
    const float* kernels = (const float*)d_in[1];
    const float* a       = (const float*)d_in[2];
    const float* b       = (const float*)d_in[3];
    float* out = (float*)d_out;

    static bool attr_set = false;
    if (!attr_set) {
        cudaFuncSetAttribute(conv_hmma_kernel,
                             cudaFuncAttributeMaxDynamicSharedMemorySize, DYN_SMEM);
        attr_set = true;
    }

    init_counts_kernel<<<1, 32>>>();
    vote_kernel<<<NPIX / 256, 256>>>(x, a, b);
    factor_kernel<<<1, 128>>>(kernels, a, b);
    conv_hmma_kernel<<<NPIX / 128, 256, DYN_SMEM>>>(kernels, x, out);
}

// round 7
// speedup vs baseline: 1.9511x; 1.1590x over previous
#include <cuda_runtime.h>
#include <cuda_bf16.h>
#include <math.h>
#include <stdint.h>

// ---- problem constants ----
#define OC     128
#define IC     64
#define SPAN   576
#define TSIZE  8
#define MLSH   5
#define HH     56
#define WW     56
#define BATCH  16
#define IMG    (HH*WW)      // 3136
#define NPIX   (BATCH*IMG)  // 50176
#define NCHUNK 9            // SPAN / 64

// ---- device scratch ----
__device__ int   g_counts[TSIZE];
__device__ float g_factor[OC];
// W split, pre-swizzled smem image: [chunk][swz(row*128 + kk*2)] (16KB/chunk)
__device__ __align__(16) unsigned short g_Whi[NCHUNK * 8192];
__device__ __align__(16) unsigned short g_Wlo[NCHUNK * 8192];
// x split packed: hi | lo<<16 per element
__device__ __align__(16) uint32_t g_xs[BATCH * IC * IMG];

// ============================================================
// helpers
// ============================================================
__device__ __forceinline__ uint32_t smem_u32(const void* p) {
    uint32_t a;
    asm("{ .reg .u64 t; cvta.to.shared.u64 t, %1; cvt.u32.u64 %0, t; }" : "=r"(a) : "l"(p));
    return a;
}
__device__ __forceinline__ uint32_t swz(uint32_t off) { return off ^ ((off >> 3) & 0x70); }

__device__ __forceinline__ void ldsm_x4(uint32_t* r, uint32_t addr) {
    asm volatile("ldmatrix.sync.aligned.m8n8.x4.shared.b16 {%0,%1,%2,%3}, [%4];"
        : "=r"(r[0]), "=r"(r[1]), "=r"(r[2]), "=r"(r[3]) : "r"(addr));
}
__device__ __forceinline__ void mma_bf16(float* c, const uint32_t* a, const uint32_t* b) {
    asm volatile(
        "mma.sync.aligned.m16n8k16.row.col.f32.bf16.bf16.f32 "
        "{%0,%1,%2,%3}, {%4,%5,%6,%7}, {%8,%9}, {%0,%1,%2,%3};"
        : "+f"(c[0]), "+f"(c[1]), "+f"(c[2]), "+f"(c[3])
        : "r"(a[0]), "r"(a[1]), "r"(a[2]), "r"(a[3]), "r"(b[0]), "r"(b[1]));
}

__device__ __forceinline__ int bucket_of(float h, float b) {
    float q = floorf((h + b) / 2.5f);
    int i = (int)q;
    int r = i % TSIZE;
    return r < 0 ? -r : r;
}

__device__ __forceinline__ uint32_t split_pack(float v) {
    __nv_bfloat16 h = __float2bfloat16(v);
    __nv_bfloat16 l = __float2bfloat16(v - __bfloat162float(h));
    return (uint32_t)__bfloat16_as_ushort(h) | ((uint32_t)__bfloat16_as_ushort(l) << 16);
}

__global__ void init_counts_kernel() {
    if (threadIdx.x < TSIZE) g_counts[threadIdx.x] = 0;
}

// ------------------------------------------------------------------
// prep_w: split W into bf16 hi/lo, stored pre-swizzled per 64-K chunk
// ------------------------------------------------------------------
__global__ __launch_bounds__(256) void prep_w_kernel(const float* __restrict__ W) {
    int ch = blockIdx.x;
    for (int i = threadIdx.x; i < 8192; i += 256) {
        int row = i >> 6, kk = i & 63;
        float v = W[row * SPAN + ch * 64 + kk];
        __nv_bfloat16 h = __float2bfloat16(v);
        __nv_bfloat16 l = __float2bfloat16(v - __bfloat162float(h));
        uint32_t off = swz((uint32_t)(row * 128 + kk * 2));
        *(unsigned short*)((char*)g_Whi + ch * 16384 + off) = __bfloat16_as_ushort(h);
        *(unsigned short*)((char*)g_Wlo + ch * 16384 + off) = __bfloat16_as_ushort(l);
    }
}

// ------------------------------------------------------------------
// prep_x: split x into packed (hi | lo<<16) uint32
// ------------------------------------------------------------------
__global__ __launch_bounds__(256) void prep_x_kernel(const float* __restrict__ x) {
    int i = blockIdx.x * 256 + threadIdx.x;       // over float4s: 802816 exact
    float4 v = ((const float4*)x)[i];
    uint4 o;
    o.x = split_pack(v.x); o.y = split_pack(v.y);
    o.z = split_pack(v.z); o.w = split_pack(v.w);
    ((uint4*)g_xs)[i] = o;
}

// ------------------------------------------------------------------
// Vote pass: one block per (batch, row). x rows cached in smem.
// ------------------------------------------------------------------
__global__ __launch_bounds__(256) void vote_kernel(
    const float* __restrict__ x, const float* __restrict__ a, const float* __restrict__ bptr)
{
    __shared__ float sx[IC * 3 * WW];     // [c][r][xx], 43008 B
    __shared__ float sa[SPAN + MLSH];
    __shared__ float partial[WW][4];
    __shared__ int hist[TSIZE];

    const int tid = threadIdx.x;
    const int b   = blockIdx.x / HH;
    const int y   = blockIdx.x % HH;

    for (int i = tid; i < SPAN + MLSH; i += 256) sa[i] = a[i];
    if (tid < TSIZE) hist[tid] = 0;

    const float* xb = x + (size_t)b * IC * IMG;
    for (int idx = tid; idx < IC * 3 * WW; idx += 256) {
        int c   = idx / (3 * WW);
        int rem = idx - c * (3 * WW);
        int r   = rem / WW;
        int xx  = rem - r * WW;
        int yy  = y + r - 1;
        sx[idx] = ((unsigned)yy < HH) ? xb[c * IMG + yy * WW + xx] : 0.0f;
    }
    __syncthreads();

    const int g  = tid >> 6;       // 0..3
    const int xx = tid & 63;       // 0..63 (>=56 idle)
    if (xx < WW) {
        float v = 0.0f;
        #pragma unroll 4
        for (int ci = 0; ci < 16; ci++) {
            int c = g * 16 + ci;
            const float* sxc = sx + c * (3 * WW);
            const float* sac = sa + c * 9;
            #pragma unroll
            for (int r = 0; r < 3; r++)
                #pragma unroll
                for (int dx = 0; dx < 3; dx++) {
                    int xq = xx + dx - 1;
                    if ((unsigned)xq < WW) v += sac[r * 3 + dx] * sxc[r * WW + xq];
                }
        }
        partial[xx][g] = v;
    }
    __syncthreads();

    if (tid < WW) {
        float v = partial[tid][0] + partial[tid][1] + partial[tid][2] + partial[tid][3];
        float q = 0.0f;
        #pragma unroll
        for (int i = 0; i < MLSH; i++) q += sa[SPAN + i];
        v += 0.5f * q;
        atomicAdd(&hist[bucket_of(v, bptr[0])], 1);
    }
    __syncthreads();
    if (tid < TSIZE) atomicAdd(&g_counts[tid], hist[tid]);
}

// ------------------------------------------------------------------
// Factor pass
// ------------------------------------------------------------------
__global__ __launch_bounds__(128) void factor_kernel(
    const float* __restrict__ kernels, const float* __restrict__ a, const float* __restrict__ bptr)
{
    __shared__ float sa[SPAN + MLSH];
    __shared__ int sh_bucket, sh_cnt;
    for (int i = threadIdx.x; i < SPAN + MLSH; i += blockDim.x) sa[i] = a[i];
    if (threadIdx.x == 0) {
        int best = 0, bi = 0;
        #pragma unroll
        for (int t = 0; t < TSIZE; t++) { int c = g_counts[t]; if (c > best) { best = c; bi = t; } }
        sh_bucket = bi; sh_cnt = 0;
    }
    __syncthreads();

    int oc = threadIdx.x;
    const float* w = kernels + (size_t)oc * SPAN;
    float dot = 0.0f, nrm = 0.0f;
    for (int k = 0; k < SPAN; k++) { float wv = w[k]; dot += wv * sa[k]; nrm += wv * wv; }
    float s = nrm, paug = 0.0f;
    #pragma unroll
    for (int i = 0; i < MLSH; i++) { paug += s * sa[SPAN + i]; s = s * s; }
    int kidx = bucket_of(dot + paug, bptr[0]);
    int in_bucket = (kidx == sh_bucket) ? 1 : 0;
    atomicAdd(&sh_cnt, in_bucket);
    __syncthreads();
    int cnt = sh_cnt;
    g_factor[oc] = (cnt > 0) ? (in_bucket ? ((float)OC / (float)cnt) : 0.0f) : 1.0f;
}

// ------------------------------------------------------------------
// HMMA bf16-split implicit GEMM, lean staging.
//   A tiles: bulk uint4 copy of pre-swizzled, pre-split W chunks.
//   B tiles: gather packed hi|lo taps, STS.128 with PER-BLOCK swizzle.
//   factor applied in epilogue.
// ------------------------------------------------------------------
#define A_HI 0
#define A_LO 16384
#define B_HI 32768
#define B_LO 49152
#define DYN_SMEM (65536 + 1024)

__global__ __launch_bounds__(256, 2)
void conv_hmma_kernel(const float* __restrict__ x_unused,
                      float* __restrict__ out)
{
    extern __shared__ char dsm[];
    char* sb = (char*)(((uintptr_t)dsm + 1023) & ~(uintptr_t)1023);
    const uint32_t sb_u = smem_u32(sb);

    const int tid  = threadIdx.x;
    const int wid  = tid >> 5;
    const int lane = tid & 31;
    const int n0   = blockIdx.x * 128;

    const int wm = wid >> 2;
    const int wn = wid & 3;

    // ---- B staging geometry: 2 threads per pixel row, 32 k each ----
    const int rown  = tid >> 1;
    const int kbase = (tid & 1) * 32;
    const int n     = n0 + rown;
    const int bimg  = n / IMG;
    const int pix   = n - bimg * IMG;
    const int y0    = pix / WW;
    const int x0    = pix - y0 * WW;
    const uint32_t* xb = g_xs + (size_t)bimg * IC * IMG;

    // ---- ldmatrix lane addresses ----
    const uint32_t a_row = (uint32_t)(wm * 64 + (lane & 15)) * 128 + ((lane >> 4) << 4);
    const uint32_t b_row = (uint32_t)(wn * 32 + (lane & 7) + ((lane >> 4) << 3)) * 128
                         + (((lane >> 3) & 1) << 4);

    float acc[4][4][4];
    #pragma unroll
    for (int i = 0; i < 4; i++)
        #pragma unroll
        for (int j = 0; j < 4; j++)
            #pragma unroll
            for (int q = 0; q < 4; q++) acc[i][j][q] = 0.0f;

    for (int ch = 0; ch < NCHUNK; ch++) {
        const int k0 = ch * 64;

        // ---- A tiles: bulk copy (pre-swizzled) ----
        {
            const uint4* wh4 = (const uint4*)((const char*)g_Whi + ch * 16384);
            const uint4* wl4 = (const uint4*)((const char*)g_Wlo + ch * 16384);
            uint4* ah = (uint4*)(sb + A_HI);
            uint4* al = (uint4*)(sb + A_LO);
            #pragma unroll
            for (int i = 0; i < 4; i++) {
                ah[tid + i * 256] = wh4[tid + i * 256];
                al[tid + i * 256] = wl4[tid + i * 256];
            }
        }

        // ---- B tiles: gather packed taps, STS.128, swizzle per 16B block ----
        #pragma unroll
        for (int p = 0; p < 4; p++) {
            uint32_t hw[4], lw[4];
            #pragma unroll
            for (int e = 0; e < 4; e++) {
                uint32_t u[2];
                #pragma unroll
                for (int t = 0; t < 2; t++) {
                    int kg = k0 + kbase + p * 8 + e * 2 + t;
                    int cc = kg / 9;
                    int rr = kg - cc * 9;
                    int dy = rr / 3;
                    int dx = rr - dy * 3;
                    int yy = y0 + dy - 1;
                    int xx = x0 + dx - 1;
                    uint32_t v = 0;
                    if ((unsigned)yy < HH && (unsigned)xx < WW)
                        v = xb[cc * IMG + yy * WW + xx];
                    u[t] = v;
                }
                hw[e] = (u[0] & 0xffffu) | (u[1] << 16);
                lw[e] = (u[0] >> 16) | (u[1] & 0xffff0000u);
            }
            // BUGFIX (R6): swizzle must be applied to the FULL offset of each
            // 16B block — XOR-then-add is not add-then-XOR.
            const uint32_t addr = swz((uint32_t)(rown * 128 + (kbase + p * 8) * 2));
            *(uint4*)(sb + B_HI + addr) = make_uint4(hw[0], hw[1], hw[2], hw[3]);
            *(uint4*)(sb + B_LO + addr) = make_uint4(lw[0], lw[1], lw[2], lw[3]);
        }
        __syncthreads();

        // ---- 4 k-steps of 16, 3 passes ----
        #pragma unroll
        for (int ks = 0; ks < 4; ks++) {
            const uint32_t kb = (uint32_t)ks * 32;
            uint32_t af[4][4], bhf[4][2], blf[4][2];

            #pragma unroll
            for (int mt = 0; mt < 4; mt++)
                ldsm_x4(af[mt], sb_u + A_HI + swz(a_row + (uint32_t)mt * 16 * 128 + kb));
            #pragma unroll
            for (int p = 0; p < 2; p++) {
                uint32_t t[4];
                ldsm_x4(t, sb_u + B_HI + swz(b_row + (uint32_t)p * 16 * 128 + kb));
                bhf[p*2+0][0] = t[0]; bhf[p*2+0][1] = t[1];
                bhf[p*2+1][0] = t[2]; bhf[p*2+1][1] = t[3];
            }
            #pragma unroll
            for (int p = 0; p < 2; p++) {
                uint32_t t[4];
                ldsm_x4(t, sb_u + B_LO + swz(b_row + (uint32_t)p * 16 * 128 + kb));
                blf[p*2+0][0] = t[0]; blf[p*2+0][1] = t[1];
                blf[p*2+1][0] = t[2]; blf[p*2+1][1] = t[3];
            }

            #pragma unroll
            for (int mt = 0; mt < 4; mt++)
                #pragma unroll
                for (int nt = 0; nt < 4; nt++) {
                    mma_bf16(acc[mt][nt], af[mt], bhf[nt]);
                    mma_bf16(acc[mt][nt], af[mt], blf[nt]);
                }
            #pragma unroll
            for (int mt = 0; mt < 4; mt++)
                ldsm_x4(af[mt], sb_u + A_LO + swz(a_row + (uint32_t)mt * 16 * 128 + kb));
            #pragma unroll
            for (int mt = 0; mt < 4; mt++)
                #pragma unroll
                for (int nt = 0; nt < 4; nt++)
                    mma_bf16(acc[mt][nt], af[mt], bhf[nt]);
        }
        __syncthreads();
    }

    // ---- epilogue: apply factor, store ----
    #pragma unroll
    for (int mt = 0; mt < 4; mt++) {
        const int m0 = wm * 64 + mt * 16 + (lane >> 2);
        const float f0 = g_factor[m0];
        const float f1 = g_factor[m0 + 8];
        #pragma unroll
        for (int nt = 0; nt < 4; nt++) {
            const int np = n0 + wn * 32 + nt * 8 + (lane & 3) * 2;
            const int bb = np / IMG;
            const int pp = np - bb * IMG;
            float* o0 = out + ((size_t)bb * OC + m0) * IMG + pp;
            *(float2*)o0             = make_float2(acc[mt][nt][0] * f0, acc[mt][nt][1] * f0);
            *(float2*)(o0 + 8 * IMG) = make_float2(acc[mt][nt][2] * f1, acc[mt][nt][3] * f1);
        }
    }
}

// ------------------------------------------------------------------
extern "C" void kernel_launch(void* const* d_in, const int* in_sizes, int n_in,
                              void* d_out, int out_size)
{
    const float* x       = (const float*)d_in[0];
    const float* kernels = (const float*)d_in[1];
    const float* a       = (const float*)d_in[2];
    const float* b       = (const float*)d_in[3];
    float* out = (float*)d_out;

    static bool attr_set = false;
    if (!attr_set) {
        cudaFuncSetAttribute(conv_hmma_kernel,
                             cudaFuncAttributeMaxDynamicSharedMemorySize, DYN_SMEM);
        attr_set = true;
    }

    init_counts_kernel<<<1, 32>>>();
    prep_w_kernel<<<NCHUNK, 256>>>(kernels);
    prep_x_kernel<<<(BATCH * IC * IMG) / 4 / 256, 256>>>(x);   // 3136 blocks exact
    vote_kernel<<<BATCH * HH, 256>>>(x, a, b);
    factor_kernel<<<1, 128>>>(kernels, a, b);
    conv_hmma_kernel<<<NPIX / 128, 256, DYN_SMEM>>>(x, out);
}

// round 8
// speedup vs baseline: 2.0203x; 1.0355x over previous
#include <cuda_runtime.h>
#include <cuda_bf16.h>
#include <math.h>
#include <stdint.h>

// ---- problem constants ----
#define OC     128
#define IC     64
#define SPAN   576
#define TSIZE  8
#define MLSH   5
#define HH     56
#define WW     56
#define BATCH  16
#define IMG    (HH*WW)      // 3136
#define NPIX   (BATCH*IMG)  // 50176
#define NCHUNK 9            // SPAN / 64

// ---- device scratch ----
__device__ int   g_counts[TSIZE];
__device__ float g_factor[OC];
// A operands in mma-fragment order:
// [ch][wm][mt][ks][hilo][lane] -> uint4 (a0..a3 of m16n8k16 A fragment)
__device__ __align__(16) uint4 g_Wfrag[NCHUNK * 2 * 4 * 4 * 2 * 32];   // 288 KB
// x split packed: hi | lo<<16 per element
__device__ __align__(16) uint32_t g_xs[BATCH * IC * IMG];

// ============================================================
// helpers
// ============================================================
__device__ __forceinline__ uint32_t smem_u32(const void* p) {
    uint32_t a;
    asm("{ .reg .u64 t; cvta.to.shared.u64 t, %1; cvt.u32.u64 %0, t; }" : "=r"(a) : "l"(p));
    return a;
}
__device__ __forceinline__ uint32_t swz(uint32_t off) { return off ^ ((off >> 3) & 0x70); }

__device__ __forceinline__ void ldsm_x4(uint32_t* r, uint32_t addr) {
    asm volatile("ldmatrix.sync.aligned.m8n8.x4.shared.b16 {%0,%1,%2,%3}, [%4];"
        : "=r"(r[0]), "=r"(r[1]), "=r"(r[2]), "=r"(r[3]) : "r"(addr));
}
__device__ __forceinline__ void mma_bf16(float* c, const uint32_t* a, const uint32_t* b) {
    asm volatile(
        "mma.sync.aligned.m16n8k16.row.col.f32.bf16.bf16.f32 "
        "{%0,%1,%2,%3}, {%4,%5,%6,%7}, {%8,%9}, {%0,%1,%2,%3};"
        : "+f"(c[0]), "+f"(c[1]), "+f"(c[2]), "+f"(c[3])
        : "r"(a[0]), "r"(a[1]), "r"(a[2]), "r"(a[3]), "r"(b[0]), "r"(b[1]));
}

__device__ __forceinline__ int bucket_of(float h, float b) {
    float q = floorf((h + b) / 2.5f);
    int i = (int)q;
    int r = i % TSIZE;
    return r < 0 ? -r : r;
}

__device__ __forceinline__ uint32_t split_pack(float v) {
    __nv_bfloat16 h = __float2bfloat16(v);
    __nv_bfloat16 l = __float2bfloat16(v - __bfloat162float(h));
    return (uint32_t)__bfloat16_as_ushort(h) | ((uint32_t)__bfloat16_as_ushort(l) << 16);
}
__device__ __forceinline__ uint32_t pack2h(float a, float b) {  // hi parts
    __nv_bfloat16 ha = __float2bfloat16(a), hb = __float2bfloat16(b);
    return (uint32_t)__bfloat16_as_ushort(ha) | ((uint32_t)__bfloat16_as_ushort(hb) << 16);
}
__device__ __forceinline__ uint32_t pack2l(float a, float b) {  // lo parts
    __nv_bfloat16 ha = __float2bfloat16(a), hb = __float2bfloat16(b);
    __nv_bfloat16 la = __float2bfloat16(a - __bfloat162float(ha));
    __nv_bfloat16 lb = __float2bfloat16(b - __bfloat162float(hb));
    return (uint32_t)__bfloat16_as_ushort(la) | ((uint32_t)__bfloat16_as_ushort(lb) << 16);
}

__global__ void init_counts_kernel() {
    if (threadIdx.x < TSIZE) g_counts[threadIdx.x] = 0;
}

// ------------------------------------------------------------------
// prep_w: build mma-fragment-ordered W (hi & lo), one lane-group/thread
// ------------------------------------------------------------------
__global__ __launch_bounds__(256) void prep_w_kernel(const float* __restrict__ W) {
    int i = blockIdx.x * 256 + threadIdx.x;     // 9216 = 36 blocks * 256
    int lane = i & 31;
    int ks   = (i >> 5) & 3;
    int mt   = (i >> 7) & 3;
    int wm   = (i >> 9) & 1;
    int ch   = i >> 10;                          // 0..8

    int r = wm * 64 + mt * 16 + (lane >> 2);
    int k = ch * 64 + ks * 16 + (lane & 3) * 2;

    float v00 = W[r * SPAN + k],           v01 = W[r * SPAN + k + 1];
    float v10 = W[(r + 8) * SPAN + k],     v11 = W[(r + 8) * SPAN + k + 1];
    float v02 = W[r * SPAN + k + 8],       v03 = W[r * SPAN + k + 9];
    float v12 = W[(r + 8) * SPAN + k + 8], v13 = W[(r + 8) * SPAN + k + 9];

    uint4 hi = make_uint4(pack2h(v00, v01), pack2h(v10, v11),
                          pack2h(v02, v03), pack2h(v12, v13));
    uint4 lo = make_uint4(pack2l(v00, v01), pack2l(v10, v11),
                          pack2l(v02, v03), pack2l(v12, v13));

    int base = (((ch * 2 + wm) * 4 + mt) * 4 + ks) * 2 * 32 + lane;
    g_Wfrag[base]      = hi;    // hilo = 0
    g_Wfrag[base + 32] = lo;    // hilo = 1
}

// ------------------------------------------------------------------
// prep_x: split x into packed (hi | lo<<16) uint32
// ------------------------------------------------------------------
__global__ __launch_bounds__(256) void prep_x_kernel(const float* __restrict__ x) {
    int i = blockIdx.x * 256 + threadIdx.x;
    float4 v = ((const float4*)x)[i];
    uint4 o;
    o.x = split_pack(v.x); o.y = split_pack(v.y);
    o.z = split_pack(v.z); o.w = split_pack(v.w);
    ((uint4*)g_xs)[i] = o;
}

// ------------------------------------------------------------------
// Vote pass: one block per (batch, row). x rows cached in smem.
// ------------------------------------------------------------------
__global__ __launch_bounds__(256) void vote_kernel(
    const float* __restrict__ x, const float* __restrict__ a, const float* __restrict__ bptr)
{
    __shared__ float sx[IC * 3 * WW];
    __shared__ float sa[SPAN + MLSH];
    __shared__ float partial[WW][4];
    __shared__ int hist[TSIZE];

    const int tid = threadIdx.x;
    const int b   = blockIdx.x / HH;
    const int y   = blockIdx.x % HH;

    for (int i = tid; i < SPAN + MLSH; i += 256) sa[i] = a[i];
    if (tid < TSIZE) hist[tid] = 0;

    const float* xb = x + (size_t)b * IC * IMG;
    for (int idx = tid; idx < IC * 3 * WW; idx += 256) {
        int c   = idx / (3 * WW);
        int rem = idx - c * (3 * WW);
        int r   = rem / WW;
        int xx  = rem - r * WW;
        int yy  = y + r - 1;
        sx[idx] = ((unsigned)yy < HH) ? xb[c * IMG + yy * WW + xx] : 0.0f;
    }
    __syncthreads();

    const int g  = tid >> 6;
    const int xx = tid & 63;
    if (xx < WW) {
        float v = 0.0f;
        #pragma unroll 4
        for (int ci = 0; ci < 16; ci++) {
            int c = g * 16 + ci;
            const float* sxc = sx + c * (3 * WW);
            const float* sac = sa + c * 9;
            #pragma unroll
            for (int r = 0; r < 3; r++)
                #pragma unroll
                for (int dx = 0; dx < 3; dx++) {
                    int xq = xx + dx - 1;
                    if ((unsigned)xq < WW) v += sac[r * 3 + dx] * sxc[r * WW + xq];
                }
        }
        partial[xx][g] = v;
    }
    __syncthreads();

    if (tid < WW) {
        float v = partial[tid][0] + partial[tid][1] + partial[tid][2] + partial[tid][3];
        float q = 0.0f;
        #pragma unroll
        for (int i = 0; i < MLSH; i++) q += sa[SPAN + i];
        v += 0.5f * q;
        atomicAdd(&hist[bucket_of(v, bptr[0])], 1);
    }
    __syncthreads();
    if (tid < TSIZE) atomicAdd(&g_counts[tid], hist[tid]);
}

// ------------------------------------------------------------------
// Factor pass
// ------------------------------------------------------------------
__global__ __launch_bounds__(128) void factor_kernel(
    const float* __restrict__ kernels, const float* __restrict__ a, const float* __restrict__ bptr)
{
    __shared__ float sa[SPAN + MLSH];
    __shared__ int sh_bucket, sh_cnt;
    for (int i = threadIdx.x; i < SPAN + MLSH; i += blockDim.x) sa[i] = a[i];
    if (threadIdx.x == 0) {
        int best = 0, bi = 0;
        #pragma unroll
        for (int t = 0; t < TSIZE; t++) { int c = g_counts[t]; if (c > best) { best = c; bi = t; } }
        sh_bucket = bi; sh_cnt = 0;
    }
    __syncthreads();

    int oc = threadIdx.x;
    const float* w = kernels + (size_t)oc * SPAN;
    float dot = 0.0f, nrm = 0.0f;
    for (int k = 0; k < SPAN; k++) { float wv = w[k]; dot += wv * sa[k]; nrm += wv * wv; }
    float s = nrm, paug = 0.0f;
    #pragma unroll
    for (int i = 0; i < MLSH; i++) { paug += s * sa[SPAN + i]; s = s * s; }
    int kidx = bucket_of(dot + paug, bptr[0]);
    int in_bucket = (kidx == sh_bucket) ? 1 : 0;
    atomicAdd(&sh_cnt, in_bucket);
    __syncthreads();
    int cnt = sh_cnt;
    g_factor[oc] = (cnt > 0) ? (in_bucket ? ((float)OC / (float)cnt) : 0.0f) : 1.0f;
}

// ------------------------------------------------------------------
// HMMA conv GEMM, pipelined:
//   A: LDG.128 fragments direct from g_Wfrag (no smem)
//   B: double-buffered smem (2 x 32KB), ONE __syncthreads per chunk
// ------------------------------------------------------------------
#define STAGE     32768     // B_HI(16K) + B_LO(16K)
#define DYN_SMEM  (2*STAGE + 1024)

// gather 16 im2col taps (packed hi|lo) for k in [k0+kb16, k0+kb16+16)
__device__ __forceinline__ void gather16(const uint32_t* __restrict__ xb,
                                         int k0, int kb16, int y0, int x0,
                                         uint32_t* u) {
    #pragma unroll
    for (int j = 0; j < 16; j++) {
        int kg = k0 + kb16 + j;
        int cc = kg / 9;
        int rr = kg - cc * 9;
        int dy = rr / 3;
        int dx = rr - dy * 3;
        int yy = y0 + dy - 1;
        int xx = x0 + dx - 1;
        uint32_t v = 0;
        if ((unsigned)yy < HH && (unsigned)xx < WW)
            v = xb[cc * IMG + yy * WW + xx];
        u[j] = v;
    }
}
// store 16 taps into a stage buffer (hi & lo planes), swizzled per 16B block
__device__ __forceinline__ void sts16(char* stage, uint32_t row_off, int kb16,
                                      const uint32_t* u) {
    #pragma unroll
    for (int p = 0; p < 2; p++) {
        uint32_t hw[4], lw[4];
        #pragma unroll
        for (int e = 0; e < 4; e++) {
            uint32_t u0 = u[p * 8 + e * 2], u1 = u[p * 8 + e * 2 + 1];
            hw[e] = (u0 & 0xffffu) | (u1 << 16);
            lw[e] = (u0 >> 16) | (u1 & 0xffff0000u);
        }
        uint32_t addr = swz(row_off + (uint32_t)(kb16 + p * 8) * 2);
        *(uint4*)(stage +         addr) = make_uint4(hw[0], hw[1], hw[2], hw[3]);
        *(uint4*)(stage + 16384 + addr) = make_uint4(lw[0], lw[1], lw[2], lw[3]);
    }
}

// one k-step (k16): A-hi LDG + B ldsm + 48 MMAs
__device__ __forceinline__ void mma_ks(uint32_t buf_u, const uint4* __restrict__ Af,
                                       int ks, uint32_t b_row, float (*acc)[4][4]) {
    const uint32_t kb = (uint32_t)ks * 32;
    uint4 af[4];
    #pragma unroll
    for (int mt = 0; mt < 4; mt++)
        af[mt] = Af[((mt * 4 + ks) * 2 + 0) * 32];           // hi fragments

    uint32_t bhf[4][2], blf[4][2];
    #pragma unroll
    for (int p = 0; p < 2; p++) {
        uint32_t t[4];
        ldsm_x4(t, buf_u + swz(b_row + (uint32_t)p * 2048 + kb));
        bhf[p*2+0][0] = t[0]; bhf[p*2+0][1] = t[1];
        bhf[p*2+1][0] = t[2]; bhf[p*2+1][1] = t[3];
    }
    #pragma unroll
    for (int p = 0; p < 2; p++) {
        uint32_t t[4];
        ldsm_x4(t, buf_u + 16384 + swz(b_row + (uint32_t)p * 2048 + kb));
        blf[p*2+0][0] = t[0]; blf[p*2+0][1] = t[1];
        blf[p*2+1][0] = t[2]; blf[p*2+1][1] = t[3];
    }

    #pragma unroll
    for (int mt = 0; mt < 4; mt++)
        #pragma unroll
        for (int nt = 0; nt < 4; nt++) {
            mma_bf16(acc[mt][nt], (const uint32_t*)&af[mt], bhf[nt]);
            mma_bf16(acc[mt][nt], (const uint32_t*)&af[mt], blf[nt]);
        }
    #pragma unroll
    for (int mt = 0; mt < 4; mt++)
        af[mt] = Af[((mt * 4 + ks) * 2 + 1) * 32];           // lo fragments
    #pragma unroll
    for (int mt = 0; mt < 4; mt++)
        #pragma unroll
        for (int nt = 0; nt < 4; nt++)
            mma_bf16(acc[mt][nt], (const uint32_t*)&af[mt], bhf[nt]);
}

__global__ __launch_bounds__(256, 2)
void conv_hmma_kernel(float* __restrict__ out)
{
    extern __shared__ char dsm[];
    char* sb = (char*)(((uintptr_t)dsm + 1023) & ~(uintptr_t)1023);
    const uint32_t sb_u = smem_u32(sb);

    const int tid  = threadIdx.x;
    const int wid  = tid >> 5;
    const int lane = tid & 31;
    const int n0   = blockIdx.x * 128;

    const int wm = wid >> 2;
    const int wn = wid & 3;

    // ---- B staging geometry: 2 threads per pixel row, 32 k each ----
    const int rown  = tid >> 1;
    const int kbase = (tid & 1) * 32;
    const int n     = n0 + rown;
    const int bimg  = n / IMG;
    const int pix   = n - bimg * IMG;
    const int y0    = pix / WW;
    const int x0    = pix - y0 * WW;
    const uint32_t* xb = g_xs + (size_t)bimg * IC * IMG;
    const uint32_t row_off = (uint32_t)rown * 128;

    // ---- B ldsm lane address ----
    const uint32_t b_row = (uint32_t)(wn * 32 + (lane & 7) + ((lane >> 4) << 3)) * 128
                         + (((lane >> 3) & 1) << 4);

    float acc[4][4][4];
    #pragma unroll
    for (int i = 0; i < 4; i++)
        #pragma unroll
        for (int j = 0; j < 4; j++)
            #pragma unroll
            for (int q = 0; q < 4; q++) acc[i][j][q] = 0.0f;

    // ---- prologue: stage chunk 0 into buffer 0 ----
    {
        uint32_t u[16];
        gather16(xb, 0, kbase, y0, x0, u);
        sts16(sb, row_off, kbase, u);
        gather16(xb, 0, kbase + 16, y0, x0, u);
        sts16(sb, row_off, kbase + 16, u);
    }
    __syncthreads();

    // ---- main loop: one sync per chunk ----
    for (int ch = 0; ch < NCHUNK; ch++) {
        const uint32_t cur_u = sb_u + (uint32_t)(ch & 1) * STAGE;
        char* nxt = sb + ((ch + 1) & 1) * STAGE;
        const uint4* Af = g_Wfrag + ch * 2048 + wm * 1024 + lane;
        const bool more = (ch + 1 < NCHUNK);

        uint32_t u[16];
        if (more) gather16(xb, (ch + 1) * 64, kbase, y0, x0, u);   // LDGs overlap MMA

        mma_ks(cur_u, Af, 0, b_row, acc);
        mma_ks(cur_u, Af, 1, b_row, acc);

        if (more) {
            sts16(nxt, row_off, kbase, u);
            gather16(xb, (ch + 1) * 64, kbase + 16, y0, x0, u);
        }

        mma_ks(cur_u, Af, 2, b_row, acc);
        mma_ks(cur_u, Af, 3, b_row, acc);

        if (more) sts16(nxt, row_off, kbase + 16, u);
        __syncthreads();
    }

    // ---- epilogue: apply factor, store ----
    #pragma unroll
    for (int mt = 0; mt < 4; mt++) {
        const int m0 = wm * 64 + mt * 16 + (lane >> 2);
        const float f0 = g_factor[m0];
        const float f1 = g_factor[m0 + 8];
        #pragma unroll
        for (int nt = 0; nt < 4; nt++) {
            const int np = n0 + wn * 32 + nt * 8 + (lane & 3) * 2;
            const int bb = np / IMG;
            const int pp = np - bb * IMG;
            float* o0 = out + ((size_t)bb * OC + m0) * IMG + pp;
            *(float2*)o0             = make_float2(acc[mt][nt][0] * f0, acc[mt][nt][1] * f0);
            *(float2*)(o0 + 8 * IMG) = make_float2(acc[mt][nt][2] * f1, acc[mt][nt][3] * f1);
        }
    }
}

// ------------------------------------------------------------------
extern "C" void kernel_launch(void* const* d_in, const int* in_sizes, int n_in,
                              void* d_out, int out_size)
{
    const float* x       = (const float*)d_in[0];
    const float* kernels = (const float*)d_in[1];
    const float* a       = (const float*)d_in[2];
    const float* b       = (const float*)d_in[3];
    float* out = (float*)d_out;

    static bool attr_set = false;
    if (!attr_set) {
        cudaFuncSetAttribute(conv_hmma_kernel,
                             cudaFuncAttributeMaxDynamicSharedMemorySize, DYN_SMEM);
        attr_set = true;
    }

    init_counts_kernel<<<1, 32>>>();
    prep_w_kernel<<<36, 256>>>(kernels);
    prep_x_kernel<<<(BATCH * IC * IMG) / 4 / 256, 256>>>(x);
    vote_kernel<<<BATCH * HH, 256>>>(x, a, b);
    factor_kernel<<<1, 128>>>(kernels, a, b);
    conv_hmma_kernel<<<NPIX / 128, 256, DYN_SMEM>>>(out);
}

// round 9
// speedup vs baseline: 2.4095x; 1.1927x over previous
#include <cuda_runtime.h>
#include <cuda_bf16.h>
#include <math.h>
#include <stdint.h>

// ---- problem constants ----
#define OC     128
#define IC     64
#define SPAN   576
#define TSIZE  8
#define MLSH   5
#define HH     56
#define WW     56
#define BATCH  16
#define IMG    (HH*WW)      // 3136
#define NPIX   (BATCH*IMG)  // 50176
#define NCHUNK 9            // SPAN / 64; with permuted k, chunk == filter tap (dy,dx)

// ---- device scratch ----
__device__ int   g_counts[TSIZE];
__device__ float g_factor[OC];
// A operands in mma-fragment order, PERMUTED k (k' = rr*64 + c):
// [ch][wm][mt][ks][hilo][lane] -> uint4
__device__ __align__(16) uint4 g_Wfrag[NCHUNK * 2 * 4 * 4 * 2 * 32];   // 288 KB
// x split packed: hi | lo<<16 per element, layout [b][c][y][x]
__device__ __align__(16) uint32_t g_xs[BATCH * IC * IMG];

// ============================================================
// helpers
// ============================================================
__device__ __forceinline__ uint32_t smem_u32(const void* p) {
    uint32_t a;
    asm("{ .reg .u64 t; cvta.to.shared.u64 t, %1; cvt.u32.u64 %0, t; }" : "=r"(a) : "l"(p));
    return a;
}
__device__ __forceinline__ uint32_t swz(uint32_t off) { return off ^ ((off >> 3) & 0x70); }

__device__ __forceinline__ void ldsm_x4(uint32_t* r, uint32_t addr) {
    asm volatile("ldmatrix.sync.aligned.m8n8.x4.shared.b16 {%0,%1,%2,%3}, [%4];"
        : "=r"(r[0]), "=r"(r[1]), "=r"(r[2]), "=r"(r[3]) : "r"(addr));
}
__device__ __forceinline__ void mma_bf16(float* c, const uint32_t* a, const uint32_t* b) {
    asm volatile(
        "mma.sync.aligned.m16n8k16.row.col.f32.bf16.bf16.f32 "
        "{%0,%1,%2,%3}, {%4,%5,%6,%7}, {%8,%9}, {%0,%1,%2,%3};"
        : "+f"(c[0]), "+f"(c[1]), "+f"(c[2]), "+f"(c[3])
        : "r"(a[0]), "r"(a[1]), "r"(a[2]), "r"(a[3]), "r"(b[0]), "r"(b[1]));
}

__device__ __forceinline__ int bucket_of(float h, float b) {
    float q = floorf((h + b) / 2.5f);
    int i = (int)q;
    int r = i % TSIZE;
    return r < 0 ? -r : r;
}

__device__ __forceinline__ uint32_t split_pack(float v) {
    __nv_bfloat16 h = __float2bfloat16(v);
    __nv_bfloat16 l = __float2bfloat16(v - __bfloat162float(h));
    return (uint32_t)__bfloat16_as_ushort(h) | ((uint32_t)__bfloat16_as_ushort(l) << 16);
}
__device__ __forceinline__ uint32_t pack2h(float a, float b) {
    __nv_bfloat16 ha = __float2bfloat16(a), hb = __float2bfloat16(b);
    return (uint32_t)__bfloat16_as_ushort(ha) | ((uint32_t)__bfloat16_as_ushort(hb) << 16);
}
__device__ __forceinline__ uint32_t pack2l(float a, float b) {
    __nv_bfloat16 ha = __float2bfloat16(a), hb = __float2bfloat16(b);
    __nv_bfloat16 la = __float2bfloat16(a - __bfloat162float(ha));
    __nv_bfloat16 lb = __float2bfloat16(b - __bfloat162float(hb));
    return (uint32_t)__bfloat16_as_ushort(la) | ((uint32_t)__bfloat16_as_ushort(lb) << 16);
}

__global__ void init_counts_kernel() {
    if (threadIdx.x < TSIZE) g_counts[threadIdx.x] = 0;
}

// ------------------------------------------------------------------
// prep_w: mma-fragment-ordered W (hi & lo) with PERMUTED k.
// fragment k-position pos (0..63 within chunk ch) -> W[..][pos*9 + ch]
// ------------------------------------------------------------------
__global__ __launch_bounds__(256) void prep_w_kernel(const float* __restrict__ W) {
    int i = blockIdx.x * 256 + threadIdx.x;     // 9216 = 36 * 256
    int lane = i & 31;
    int ks   = (i >> 5) & 3;
    int mt   = (i >> 7) & 3;
    int wm   = (i >> 9) & 1;
    int ch   = i >> 10;                          // 0..8  (= rr = kh*3+kw)

    int r   = wm * 64 + mt * 16 + (lane >> 2);
    int pos = ks * 16 + (lane & 3) * 2;          // channel index base

    const float* Wr  = W + (size_t)r * SPAN + ch;
    const float* Wr8 = Wr + 8 * SPAN;

    float v00 = Wr[pos * 9],        v01 = Wr[(pos + 1) * 9];
    float v02 = Wr[(pos + 8) * 9],  v03 = Wr[(pos + 9) * 9];
    float v10 = Wr8[pos * 9],       v11 = Wr8[(pos + 1) * 9];
    float v12 = Wr8[(pos + 8) * 9], v13 = Wr8[(pos + 9) * 9];

    uint4 hi = make_uint4(pack2h(v00, v01), pack2h(v10, v11),
                          pack2h(v02, v03), pack2h(v12, v13));
    uint4 lo = make_uint4(pack2l(v00, v01), pack2l(v10, v11),
                          pack2l(v02, v03), pack2l(v12, v13));

    int base = (((ch * 2 + wm) * 4 + mt) * 4 + ks) * 2 * 32 + lane;
    g_Wfrag[base]      = hi;
    g_Wfrag[base + 32] = lo;
}

// ------------------------------------------------------------------
// prep_x: split x into packed (hi | lo<<16) uint32
// ------------------------------------------------------------------
__global__ __launch_bounds__(256) void prep_x_kernel(const float* __restrict__ x) {
    int i = blockIdx.x * 256 + threadIdx.x;
    float4 v = ((const float4*)x)[i];
    uint4 o;
    o.x = split_pack(v.x); o.y = split_pack(v.y);
    o.z = split_pack(v.z); o.w = split_pack(v.w);
    ((uint4*)g_xs)[i] = o;
}

// ------------------------------------------------------------------
// Vote pass: one block per (batch, row). x rows cached in smem.
// ------------------------------------------------------------------
__global__ __launch_bounds__(256) void vote_kernel(
    const float* __restrict__ x, const float* __restrict__ a, const float* __restrict__ bptr)
{
    __shared__ float sx[IC * 3 * WW];
    __shared__ float sa[SPAN + MLSH];
    __shared__ float partial[WW][4];
    __shared__ int hist[TSIZE];

    const int tid = threadIdx.x;
    const int b   = blockIdx.x / HH;
    const int y   = blockIdx.x % HH;

    for (int i = tid; i < SPAN + MLSH; i += 256) sa[i] = a[i];
    if (tid < TSIZE) hist[tid] = 0;

    const float* xb = x + (size_t)b * IC * IMG;
    for (int idx = tid; idx < IC * 3 * WW; idx += 256) {
        int c   = idx / (3 * WW);
        int rem = idx - c * (3 * WW);
        int r   = rem / WW;
        int xx  = rem - r * WW;
        int yy  = y + r - 1;
        sx[idx] = ((unsigned)yy < HH) ? xb[c * IMG + yy * WW + xx] : 0.0f;
    }
    __syncthreads();

    const int g  = tid >> 6;
    const int xx = tid & 63;
    if (xx < WW) {
        float v = 0.0f;
        #pragma unroll 4
        for (int ci = 0; ci < 16; ci++) {
            int c = g * 16 + ci;
            const float* sxc = sx + c * (3 * WW);
            const float* sac = sa + c * 9;
            #pragma unroll
            for (int r = 0; r < 3; r++)
                #pragma unroll
                for (int dx = 0; dx < 3; dx++) {
                    int xq = xx + dx - 1;
                    if ((unsigned)xq < WW) v += sac[r * 3 + dx] * sxc[r * WW + xq];
                }
        }
        partial[xx][g] = v;
    }
    __syncthreads();

    if (tid < WW) {
        float v = partial[tid][0] + partial[tid][1] + partial[tid][2] + partial[tid][3];
        float q = 0.0f;
        #pragma unroll
        for (int i = 0; i < MLSH; i++) q += sa[SPAN + i];
        v += 0.5f * q;
        atomicAdd(&hist[bucket_of(v, bptr[0])], 1);
    }
    __syncthreads();
    if (tid < TSIZE) atomicAdd(&g_counts[tid], hist[tid]);
}

// ------------------------------------------------------------------
// Factor pass
// ------------------------------------------------------------------
__global__ __launch_bounds__(128) void factor_kernel(
    const float* __restrict__ kernels, const float* __restrict__ a, const float* __restrict__ bptr)
{
    __shared__ float sa[SPAN + MLSH];
    __shared__ int sh_bucket, sh_cnt;
    for (int i = threadIdx.x; i < SPAN + MLSH; i += blockDim.x) sa[i] = a[i];
    if (threadIdx.x == 0) {
        int best = 0, bi = 0;
        #pragma unroll
        for (int t = 0; t < TSIZE; t++) { int c = g_counts[t]; if (c > best) { best = c; bi = t; } }
        sh_bucket = bi; sh_cnt = 0;
    }
    __syncthreads();

    int oc = threadIdx.x;
    const float* w = kernels + (size_t)oc * SPAN;
    float dot = 0.0f, nrm = 0.0f;
    for (int k = 0; k < SPAN; k++) { float wv = w[k]; dot += wv * sa[k]; nrm += wv * wv; }
    float s = nrm, paug = 0.0f;
    #pragma unroll
    for (int i = 0; i < MLSH; i++) { paug += s * sa[SPAN + i]; s = s * s; }
    int kidx = bucket_of(dot + paug, bptr[0]);
    int in_bucket = (kidx == sh_bucket) ? 1 : 0;
    atomicAdd(&sh_cnt, in_bucket);
    __syncthreads();
    int cnt = sh_cnt;
    g_factor[oc] = (cnt > 0) ? (in_bucket ? ((float)OC / (float)cnt) : 0.0f) : 1.0f;
}

// ------------------------------------------------------------------
// HMMA conv GEMM with permuted k:
//   chunk ch == filter tap (dy,dx); within chunk, k' = channel.
//   B gather: ONE bounds test per chunk, stride-IMG loads.
//   A: LDG.128 fragments direct from g_Wfrag. B double-buffered smem.
// ------------------------------------------------------------------
#define STAGE     32768     // B_HI(16K) + B_LO(16K)
#define DYN_SMEM  (2*STAGE + 1024)

// load 16 channel taps from base (stride IMG), predicated
__device__ __forceinline__ void gather16p(const uint32_t* __restrict__ base,
                                          bool valid, uint32_t* u) {
    #pragma unroll
    for (int j = 0; j < 16; j++)
        u[j] = valid ? base[j * IMG] : 0u;
}
// store 16 taps into a stage buffer (hi & lo planes), swizzled per 16B block
__device__ __forceinline__ void sts16(char* stage, uint32_t row_off, int kb16,
                                      const uint32_t* u) {
    #pragma unroll
    for (int p = 0; p < 2; p++) {
        uint32_t hw[4], lw[4];
        #pragma unroll
        for (int e = 0; e < 4; e++) {
            uint32_t u0 = u[p * 8 + e * 2], u1 = u[p * 8 + e * 2 + 1];
            hw[e] = (u0 & 0xffffu) | (u1 << 16);
            lw[e] = (u0 >> 16) | (u1 & 0xffff0000u);
        }
        uint32_t addr = swz(row_off + (uint32_t)(kb16 + p * 8) * 2);
        *(uint4*)(stage +         addr) = make_uint4(hw[0], hw[1], hw[2], hw[3]);
        *(uint4*)(stage + 16384 + addr) = make_uint4(lw[0], lw[1], lw[2], lw[3]);
    }
}

// one k-step (k16): A LDG + B ldsm + 48 MMAs
__device__ __forceinline__ void mma_ks(uint32_t buf_u, const uint4* __restrict__ Af,
                                       int ks, uint32_t b_row, float (*acc)[4][4]) {
    const uint32_t kb = (uint32_t)ks * 32;
    uint4 af[4];
    #pragma unroll
    for (int mt = 0; mt < 4; mt++)
        af[mt] = Af[((mt * 4 + ks) * 2 + 0) * 32];           // hi fragments

    uint32_t bhf[4][2], blf[4][2];
    #pragma unroll
    for (int p = 0; p < 2; p++) {
        uint32_t t[4];
        ldsm_x4(t, buf_u + swz(b_row + (uint32_t)p * 2048 + kb));
        bhf[p*2+0][0] = t[0]; bhf[p*2+0][1] = t[1];
        bhf[p*2+1][0] = t[2]; bhf[p*2+1][1] = t[3];
    }
    #pragma unroll
    for (int p = 0; p < 2; p++) {
        uint32_t t[4];
        ldsm_x4(t, buf_u + 16384 + swz(b_row + (uint32_t)p * 2048 + kb));
        blf[p*2+0][0] = t[0]; blf[p*2+0][1] = t[1];
        blf[p*2+1][0] = t[2]; blf[p*2+1][1] = t[3];
    }

    #pragma unroll
    for (int mt = 0; mt < 4; mt++)
        #pragma unroll
        for (int nt = 0; nt < 4; nt++) {
            mma_bf16(acc[mt][nt], (const uint32_t*)&af[mt], bhf[nt]);
            mma_bf16(acc[mt][nt], (const uint32_t*)&af[mt], blf[nt]);
        }
    #pragma unroll
    for (int mt = 0; mt < 4; mt++)
        af[mt] = Af[((mt * 4 + ks) * 2 + 1) * 32];           // lo fragments
    #pragma unroll
    for (int mt = 0; mt < 4; mt++)
        #pragma unroll
        for (int nt = 0; nt < 4; nt++)
            mma_bf16(acc[mt][nt], (const uint32_t*)&af[mt], bhf[nt]);
}

__global__ __launch_bounds__(256, 2)
void conv_hmma_kernel(float* __restrict__ out)
{
    extern __shared__ char dsm[];
    char* sb = (char*)(((uintptr_t)dsm + 1023) & ~(uintptr_t)1023);
    const uint32_t sb_u = smem_u32(sb);

    const int tid  = threadIdx.x;
    const int wid  = tid >> 5;
    const int lane = tid & 31;
    const int n0   = blockIdx.x * 128;

    const int wm = wid >> 2;
    const int wn = wid & 3;

    // ---- B staging geometry: 2 threads per pixel row, 32 channels each ----
    const int rown  = tid >> 1;
    const int kbase = (tid & 1) * 32;
    const int n     = n0 + rown;
    const int bimg  = n / IMG;
    const int pix   = n - bimg * IMG;
    const int y0    = pix / WW;
    const int x0    = pix - y0 * WW;
    const uint32_t* xk = g_xs + (size_t)bimg * IC * IMG + kbase * IMG;  // channel-offset base
    const uint32_t row_off = (uint32_t)rown * 128;

    // ---- B ldsm lane address ----
    const uint32_t b_row = (uint32_t)(wn * 32 + (lane & 7) + ((lane >> 4) << 3)) * 128
                         + (((lane >> 3) & 1) << 4);

    float acc[4][4][4];
    #pragma unroll
    for (int i = 0; i < 4; i++)
        #pragma unroll
        for (int j = 0; j < 4; j++)
            #pragma unroll
            for (int q = 0; q < 4; q++) acc[i][j][q] = 0.0f;

    // ---- prologue: stage chunk 0 (tap dy=0,dx=0 -> yy=y0-1, xx=x0-1) ----
    {
        const int yy = y0 - 1, xx = x0 - 1;
        const bool valid = ((unsigned)yy < HH) && ((unsigned)xx < WW);
        const uint32_t* basep = xk + yy * WW + xx;
        uint32_t u[16];
        gather16p(basep, valid, u);
        sts16(sb, row_off, kbase, u);
        gather16p(basep + 16 * IMG, valid, u);
        sts16(sb, row_off, kbase + 16, u);
    }
    __syncthreads();

    // ---- main loop: one sync per chunk ----
    for (int ch = 0; ch < NCHUNK; ch++) {
        const uint32_t cur_u = sb_u + (uint32_t)(ch & 1) * STAGE;
        char* nxt = sb + ((ch + 1) & 1) * STAGE;
        const uint4* Af = g_Wfrag + ch * 2048 + wm * 1024 + lane;
        const bool more = (ch + 1 < NCHUNK);

        // next tap geometry (single bounds test per chunk)
        const int chn = ch + 1;
        const int dyn = chn / 3, dxn = chn - dyn * 3;
        const int yy  = y0 + dyn - 1, xx = x0 + dxn - 1;
        const bool valid = more && ((unsigned)yy < HH) && ((unsigned)xx < WW);
        const uint32_t* basep = xk + yy * WW + xx;

        uint32_t u[16];
        if (more) gather16p(basep, valid, u);        // LDGs overlap MMA

        mma_ks(cur_u, Af, 0, b_row, acc);
        mma_ks(cur_u, Af, 1, b_row, acc);

        if (more) {
            sts16(nxt, row_off, kbase, u);
            gather16p(basep + 16 * IMG, valid, u);
        }

        mma_ks(cur_u, Af, 2, b_row, acc);
        mma_ks(cur_u, Af, 3, b_row, acc);

        if (more) sts16(nxt, row_off, kbase + 16, u);
        __syncthreads();
    }

    // ---- epilogue: apply factor, store ----
    #pragma unroll
    for (int mt = 0; mt < 4; mt++) {
        const int m0 = wm * 64 + mt * 16 + (lane >> 2);
        const float f0 = g_factor[m0];
        const float f1 = g_factor[m0 + 8];
        #pragma unroll
        for (int nt = 0; nt < 4; nt++) {
            const int np = n0 + wn * 32 + nt * 8 + (lane & 3) * 2;
            const int bb = np / IMG;
            const int pp = np - bb * IMG;
            float* o0 = out + ((size_t)bb * OC + m0) * IMG + pp;
            *(float2*)o0             = make_float2(acc[mt][nt][0] * f0, acc[mt][nt][1] * f0);
            *(float2*)(o0 + 8 * IMG) = make_float2(acc[mt][nt][2] * f1, acc[mt][nt][3] * f1);
        }
    }
}

// ------------------------------------------------------------------
extern "C" void kernel_launch(void* const* d_in, const int* in_sizes, int n_in,
                              void* d_out, int out_size)
{
    const float* x       = (const float*)d_in[0];
    const float* kernels = (const float*)d_in[1];
    const float* a       = (const float*)d_in[2];
    const float* b       = (const float*)d_in[3];
    float* out = (float*)d_out;

    static bool attr_set = false;
    if (!attr_set) {
        cudaFuncSetAttribute(conv_hmma_kernel,
                             cudaFuncAttributeMaxDynamicSharedMemorySize, DYN_SMEM);
        attr_set = true;
    }

    init_counts_kernel<<<1, 32>>>();
    prep_w_kernel<<<36, 256>>>(kernels);
    prep_x_kernel<<<(BATCH * IC * IMG) / 4 / 256, 256>>>(x);
    vote_kernel<<<BATCH * HH, 256>>>(x, a, b);
    factor_kernel<<<1, 128>>>(kernels, a, b);
    conv_hmma_kernel<<<NPIX / 128, 256, DYN_SMEM>>>(out);
}